// round 3
// baseline (speedup 1.0000x reference)
#include <cuda_runtime.h>

#define B_   4
#define C_   19
#define HI   64
#define WI   128
#define HO   512
#define WO   1024
#define NPIX   (B_*HO*WO)
#define NBLK   (4*512*4)
#define LOG2E  1.4426950408889634f
#define LN2f   0.6931471805599453f

// ---------------- device scratch (zero at module load; each call re-zeroes at end) ----
__device__ float    g_oh[2][2][64];     // [loss][{cnt,sum}][slot]
__device__ float    g_bce4[B_][4][32];  // [sample][{S1,S0,pos,neg}][slot]
__device__ int      g_m[2];             // compacted count per loss (probs > 0.7)
__device__ unsigned g_done;
__device__ uint2    g_comp[2][NPIX];    // {prob_bits, nll_bits or -1e30 sentinel}

__global__ __launch_bounds__(256) void fused_kernel(
    const float* __restrict__ mainp,
    const float* __restrict__ coarsep,
    const int*   __restrict__ seg,
    const float* __restrict__ bp,
    const float* __restrict__ bgt,
    float* __restrict__ out,
    int K)
{
    __shared__ float  raw[2][C_][40];
    __shared__ float2 pr [2][C_][40];
    __shared__ float  sred[8][8];
    __shared__ bool   amLast;
    __shared__ unsigned hist[2048];
    __shared__ int      s_r;
    __shared__ unsigned s_pref;
    __shared__ float    s_bcast;
    __shared__ float    redS[8], redC[8];
    __shared__ double   shb[4];
    __shared__ float    shoh[2][4];

    const float SY = 63.f / 511.f;
    const float SX = 127.f / 1023.f;

    const int tid  = threadIdx.x;
    const int lane = tid & 31;
    const int warp = tid >> 5;
    const int oy = blockIdx.y;
    const int b  = blockIdx.z;
    const int xs = blockIdx.x * 256;

    float fy = oy * SY;
    int   y0 = (int)fy;
    int   y1 = min(y0 + 1, HI - 1);
    float wy = fy - (float)y0;

    int xbase = (int)((float)xs * SX);
    int xlast = (int)((float)(xs + 255) * SX);
    int ntot  = xlast + 2 - xbase;          // columns [xbase, xlast+1], <= 34

    const float* p0 = mainp   + (size_t)b * C_ * HI * WI;
    const float* p1 = coarsep + (size_t)b * C_ * HI * WI;

    // stage 1: vertical lerp into raw (pre-scaled by log2e)
    for (int idx = tid; idx < C_ * ntot; idx += 256) {
        int c  = idx / ntot;
        int xo = idx - c * ntot;
        int xi = min(xbase + xo, WI - 1);
        int o0 = c * HI * WI + y0 * WI + xi;
        int o1 = c * HI * WI + y1 * WI + xi;
        float a0 = p0[o0], a1 = p0[o1];
        raw[0][c][xo] = fmaf(wy, a1 - a0, a0) * LOG2E;
        float b0 = p1[o0], b1 = p1[o1];
        raw[1][c][xo] = fmaf(wy, b1 - b0, b0) * LOG2E;
    }
    __syncthreads();

    // stage 2: build (value, diff) pairs so inner loop is a single LDS.64
    {
        int n1 = ntot - 1;
        const float* rf = &raw[0][0][0];
        float2*      pf = &pr[0][0][0];
        for (int idx = tid; idx < 2 * C_ * n1; idx += 256) {
            int row = idx / n1;
            int xo  = idx - row * n1;
            float a  = rf[row * 40 + xo];
            float bb = rf[row * 40 + xo + 1];
            pf[row * 40 + xo] = make_float2(a, bb - a);
        }
    }
    __syncthreads();

    int   ox = xs + tid;
    float fx = (float)ox * SX;
    int   x0 = (int)fx;
    float wx = fx - (float)x0;
    int   i0 = x0 - xbase;

    int  pix   = (b * HO + oy) * WO + ox;
    int  t     = seg[pix];
    bool valid = (t != 255);
    int  tc    = valid ? t : 0;
    if (tc >= C_) tc = C_ - 1;

    float nll_v[2]; bool le_v[2];

    #pragma unroll
    for (int l = 0; l < 2; l++) {
        float s0 = 0.f, s1 = 0.f;
        #pragma unroll
        for (int c = 0; c < C_; c++) {
            float2 q = pr[l][c][i0];
            float e = exp2f(fmaf(wx, q.y, q.x));
            if (c & 1) s1 += e; else s0 += e;
        }
        float s = s0 + s1;
        float2 qt = pr[l][tc][i0];
        float vt  = fmaf(wx, qt.y, qt.x);
        float lp2 = vt - __log2f(s);          // log2(prob at target)
        float prob = exp2f(lp2);
        float nll  = -lp2 * LN2f;
        if (!valid) prob = 1.0f;

        le_v[l]  = valid && (prob <= 0.7f);
        nll_v[l] = le_v[l] ? nll : 0.f;

        bool gtt = prob > 0.7f;
        unsigned ball = __ballot_sync(0xffffffffu, gtt);
        if (ball) {
            int ldr = __ffs(ball) - 1;
            int base = 0;
            if (lane == ldr) base = atomicAdd(&g_m[l], __popc(ball));
            base = __shfl_sync(0xffffffffu, base, ldr);
            if (gtt) {
                int rank = __popc(ball & ((1u << lane) - 1u));
                g_comp[l][base + rank] =
                    make_uint2(__float_as_uint(prob),
                               __float_as_uint(valid ? nll : -1e30f));
            }
        }
    }

    // ---- boundary BCE (fused) ----
    float tb = bgt[pix];
    const float* pb = bp + (size_t)b * HI * WI;
    int x1 = min(x0 + 1, WI - 1);
    float v00 = pb[y0 * WI + x0], v01 = pb[y0 * WI + x1];
    float v10 = pb[y1 * WI + x0], v11 = pb[y1 * WI + x1];
    float top = fmaf(wx, v01 - v00, v00);
    float bot = fmaf(wx, v11 - v10, v10);
    float p   = fmaf(wy, bot - top, top);

    bool  isP = (tb == 1.0f), isN = (tb == 0.0f);
    float r4 = isP ? -fmaxf(__logf(p), -100.f) : 0.f;
    float r5 = isN ? -fmaxf(__logf(1.f - p), -100.f) : 0.f;

    // ---- block reduce: counts via ballot/popc, sums via shfl ----
    float c0 = (float)__popc(__ballot_sync(~0u, le_v[0]));
    float c1 = (float)__popc(__ballot_sync(~0u, le_v[1]));
    float cp = (float)__popc(__ballot_sync(~0u, isP));
    float cn = (float)__popc(__ballot_sync(~0u, isN));
    float r1 = nll_v[0], r3 = nll_v[1];
    #pragma unroll
    for (int o = 16; o > 0; o >>= 1) {
        r1 += __shfl_down_sync(~0u, r1, o);
        r3 += __shfl_down_sync(~0u, r3, o);
        r4 += __shfl_down_sync(~0u, r4, o);
        r5 += __shfl_down_sync(~0u, r5, o);
    }
    if (lane == 0) {
        sred[warp][0] = c0; sred[warp][1] = r1; sred[warp][2] = c1; sred[warp][3] = r3;
        sred[warp][4] = r4; sred[warp][5] = r5; sred[warp][6] = cp; sred[warp][7] = cn;
    }
    __syncthreads();
    if (tid < 8) {
        float acc = 0.f;
        #pragma unroll
        for (int w = 0; w < 8; w++) acc += sred[w][tid];
        int blk = blockIdx.x + 4 * (blockIdx.y + 512 * blockIdx.z);
        if (tid < 4) atomicAdd(&g_oh[tid >> 1][tid & 1][blk & 63], acc);
        else         atomicAdd(&g_bce4[b][tid - 4][blk & 31], acc);
    }

    // ---- last-block tail: fallback select + finalize + scratch reset ----
    __threadfence();
    __syncthreads();
    if (tid == 0) {
        unsigned v = atomicAdd(&g_done, 1u);
        amLast = (v == (unsigned)(NBLK - 1));
    }
    __syncthreads();
    if (!amLast) return;

    float exS[2] = {0.f, 0.f}, exC[2] = {0.f, 0.f};   // used at tid==0 only

    for (int l = 0; l < 2; l++) {
        if (tid == 0) {
            float c = 0.f;
            #pragma unroll
            for (int i = 0; i < 64; i++) c += __ldcg(&g_oh[l][0][i]);
            s_bcast = c;
        }
        __syncthreads();
        int cLE = (int)(s_bcast + 0.5f);
        __syncthreads();
        if (cLE >= K) continue;                 // common path: thr = 0.7 exactly

        int m = __ldcg(&g_m[l]);
        if (tid == 0) { s_r = K - 1 - cLE; s_pref = 0u; }
        __syncthreads();

        #pragma unroll
        for (int lev = 0; lev < 3; lev++) {
            for (int i = tid; i < 2048; i += 256) hist[i] = 0u;
            __syncthreads();
            unsigned pref = s_pref;
            for (int i = tid; i < m; i += 256) {
                unsigned bits = __ldcg(&g_comp[l][i].x);
                bool ok; unsigned bin;
                if (lev == 0)      { ok = true;                 bin = bits >> 21; }
                else if (lev == 1) { ok = (bits >> 21) == pref; bin = (bits >> 10) & 0x7FFu; }
                else               { ok = (bits >> 10) == pref; bin = bits & 0x3FFu; }
                if (ok) atomicAdd(&hist[bin], 1u);
            }
            __syncthreads();
            if (tid == 0) {
                int rr = s_r; unsigned cum = 0u;
                int nb = (lev == 2) ? 1024 : 2048;
                for (int i2 = 0; i2 < nb; i2++) {
                    unsigned h = hist[i2];
                    if ((int)(cum + h) > rr) {
                        s_pref = (lev == 0) ? (unsigned)i2
                               : (lev == 1) ? ((pref << 11) | (unsigned)i2)
                                            : ((pref << 10) | (unsigned)i2);
                        s_r = rr - (int)cum;
                        break;
                    }
                    cum += h;
                }
            }
            __syncthreads();
        }
        unsigned thr_bits = s_pref;

        float es = 0.f, ec = 0.f;
        for (int i = tid; i < m; i += 256) {
            unsigned pbits = __ldcg(&g_comp[l][i].x);
            float nl = __uint_as_float(__ldcg(&g_comp[l][i].y));
            if (pbits <= thr_bits && nl > -1e29f) { es += nl; ec += 1.f; }
        }
        #pragma unroll
        for (int o = 16; o > 0; o >>= 1) {
            es += __shfl_down_sync(~0u, es, o);
            ec += __shfl_down_sync(~0u, ec, o);
        }
        if (lane == 0) { redS[warp] = es; redC[warp] = ec; }
        __syncthreads();
        if (tid == 0) {
            float ts = 0.f, tc2 = 0.f;
            #pragma unroll
            for (int i = 0; i < 8; i++) { ts += redS[i]; tc2 += redC[i]; }
            exS[l] = ts; exC[l] = tc2;
        }
        __syncthreads();
    }

    // ---- finalize (first 128 threads) ----
    if (tid < 128) {
        int la = tid & 31, w = tid >> 5;
        float bs1  = __ldcg(&g_bce4[w][0][la]);
        float bs0  = __ldcg(&g_bce4[w][1][la]);
        float bpos = __ldcg(&g_bce4[w][2][la]);
        float bneg = __ldcg(&g_bce4[w][3][la]);
        float oc = 0.f, os = 0.f, oc1 = 0.f, os1 = 0.f;
        if (w < 2) {
            oc  = __ldcg(&g_oh[0][0][tid]); os  = __ldcg(&g_oh[0][1][tid]);
            oc1 = __ldcg(&g_oh[1][0][tid]); os1 = __ldcg(&g_oh[1][1][tid]);
        }
        #pragma unroll
        for (int o = 16; o > 0; o >>= 1) {
            bs1 += __shfl_down_sync(~0u, bs1, o); bs0 += __shfl_down_sync(~0u, bs0, o);
            bpos += __shfl_down_sync(~0u, bpos, o); bneg += __shfl_down_sync(~0u, bneg, o);
            oc += __shfl_down_sync(~0u, oc, o); os += __shfl_down_sync(~0u, os, o);
            oc1 += __shfl_down_sync(~0u, oc1, o); os1 += __shfl_down_sync(~0u, os1, o);
        }
        if (la == 0) {
            double denom = (double)bpos + (double)bneg;
            shb[w] = ((double)bneg * (double)bs1 + (double)bpos * (double)bs0) / denom;
            if (w < 2) { shoh[w][0] = oc; shoh[w][1] = os; shoh[w][2] = oc1; shoh[w][3] = os1; }
        }
    }
    __syncthreads();
    if (tid == 0) {
        double cnt0 = (double)shoh[0][0] + (double)shoh[1][0] + (double)exC[0];
        double sum0 = (double)shoh[0][1] + (double)shoh[1][1] + (double)exS[0];
        double cnt1 = (double)shoh[0][2] + (double)shoh[1][2] + (double)exC[1];
        double sum1 = (double)shoh[0][3] + (double)shoh[1][3] + (double)exS[1];
        if (cnt0 < 1.0) cnt0 = 1.0;
        if (cnt1 < 1.0) cnt1 = 1.0;
        double bce = (shb[0] + shb[1] + shb[2] + shb[3]) / (double)NPIX;
        out[0] = (float)(sum0 / cnt0 + sum1 / cnt1 + bce);
    }

    // ---- reset scratch to zero for next call/replay ----
    __syncthreads();
    {
        float* oh = &g_oh[0][0][0];
        if (tid < 256) oh[tid] = 0.f;
        float* bb = &g_bce4[0][0][0];
        for (int j = tid; j < B_ * 4 * 32; j += 256) bb[j] = 0.f;
        if (tid < 2) g_m[tid] = 0;
        if (tid == 0) g_done = 0u;
    }
}

// ---------------- launch ----------------
extern "C" void kernel_launch(void* const* d_in, const int* in_sizes, int n_in,
                              void* d_out, int out_size)
{
    const float* mainp   = (const float*)d_in[0];
    const float* coarsep = (const float*)d_in[1];
    const float* bp      = (const float*)d_in[2];
    const int*   seg     = (const int*)d_in[3];
    const float* bgt     = (const float*)d_in[4];

    int nseg = in_sizes[3];
    int K = (nseg < 100000) ? nseg : 100000;

    fused_kernel<<<dim3(WO / 256, HO, B_), 256>>>(
        mainp, coarsep, seg, bp, bgt, (float*)d_out, K);
}

// round 4
// speedup vs baseline: 1.0144x; 1.0144x over previous
#include <cuda_runtime.h>

#define B_   4
#define C_   19
#define HI   64
#define WI   128
#define HO   512
#define WO   1024
#define NPIX   (B_*HO*WO)
#define LOG2E  1.4426950408889634f
#define LN2f   0.6931471805599453f

// ---------------- device scratch (zero at module load; tail kernel re-zeroes) ----
__device__ float    g_oh[2][2][64];     // [loss][{cnt,sum}][slot]
__device__ float    g_bce4[B_][4][32];  // [sample][{S1,S0,pos,neg}][slot]
__device__ int      g_m[2];             // compacted count per loss (probs > 0.7)
__device__ uint2    g_comp[2][NPIX];    // {prob_bits, nll_bits or -1e30 sentinel}

__device__ __forceinline__ float ex2(float x) {
    float y;
    asm("ex2.approx.f32 %0, %1;" : "=f"(y) : "f"(x));
    return y;
}

// ---------------- fused: upsample + softmax + OHEM accumulate + compaction + BCE ----
__global__ __launch_bounds__(256) void compute_kernel(
    const float* __restrict__ mainp,
    const float* __restrict__ coarsep,
    const int*   __restrict__ seg,
    const float* __restrict__ bp,
    const float* __restrict__ bgt)
{
    __shared__ float  raw[2][C_][40];
    __shared__ float2 pr [2][C_][40];
    __shared__ float  sred[8][8];

    const float SY = 63.f / 511.f;
    const float SX = 127.f / 1023.f;

    const int tid  = threadIdx.x;
    const int lane = tid & 31;
    const int warp = tid >> 5;
    const int oy = blockIdx.y;
    const int b  = blockIdx.z;
    const int xs = blockIdx.x * 256;

    float fy = oy * SY;
    int   y0 = (int)fy;
    int   y1 = min(y0 + 1, HI - 1);
    float wy = fy - (float)y0;

    int xbase = (int)((float)xs * SX);
    int xlast = (int)((float)(xs + 255) * SX);
    int ntot  = xlast + 2 - xbase;          // columns [xbase, xlast+1], <= 34

    const float* p0 = mainp   + (size_t)b * C_ * HI * WI;
    const float* p1 = coarsep + (size_t)b * C_ * HI * WI;

    // stage 1: vertical lerp (pre-scaled by log2e)
    for (int idx = tid; idx < C_ * ntot; idx += 256) {
        int c  = idx / ntot;
        int xo = idx - c * ntot;
        int xi = min(xbase + xo, WI - 1);
        int o0 = c * HI * WI + y0 * WI + xi;
        int o1 = c * HI * WI + y1 * WI + xi;
        float a0 = p0[o0], a1 = p0[o1];
        raw[0][c][xo] = fmaf(wy, a1 - a0, a0) * LOG2E;
        float b0 = p1[o0], b1 = p1[o1];
        raw[1][c][xo] = fmaf(wy, b1 - b0, b0) * LOG2E;
    }
    __syncthreads();

    // stage 2: (value, diff) pairs -> inner loop is LDS.64 + FMA + EX2 + FADD
    {
        int n1 = ntot - 1;
        const float* rf = &raw[0][0][0];
        float2*      pf = &pr[0][0][0];
        for (int idx = tid; idx < 2 * C_ * n1; idx += 256) {
            int row = idx / n1;
            int xo  = idx - row * n1;
            float a  = rf[row * 40 + xo];
            float bb = rf[row * 40 + xo + 1];
            pf[row * 40 + xo] = make_float2(a, bb - a);
        }
    }
    __syncthreads();

    int   ox = xs + tid;
    float fx = (float)ox * SX;
    int   x0 = (int)fx;
    float wx = fx - (float)x0;
    int   i0 = x0 - xbase;

    int  pix   = (b * HO + oy) * WO + ox;
    int  t     = seg[pix];
    bool valid = (t != 255);
    int  tc    = valid ? t : 0;
    if (tc >= C_) tc = C_ - 1;

    float nll_v[2]; bool le_v[2];

    #pragma unroll
    for (int l = 0; l < 2; l++) {
        float s0 = 0.f, s1 = 0.f;
        #pragma unroll
        for (int c = 0; c < C_; c++) {
            float2 q = pr[l][c][i0];
            float e = ex2(fmaf(wx, q.y, q.x));
            if (c & 1) s1 += e; else s0 += e;
        }
        float s = s0 + s1;
        float2 qt = pr[l][tc][i0];
        float vt  = fmaf(wx, qt.y, qt.x);
        float lp2 = vt - __log2f(s);          // log2(prob at target)
        float prob = ex2(lp2);
        float nll  = -lp2 * LN2f;
        if (!valid) prob = 1.0f;

        le_v[l]  = valid && (prob <= 0.7f);
        nll_v[l] = le_v[l] ? nll : 0.f;

        bool gtt = prob > 0.7f;
        unsigned ball = __ballot_sync(0xffffffffu, gtt);
        if (ball) {
            int ldr = __ffs(ball) - 1;
            int base = 0;
            if (lane == ldr) base = atomicAdd(&g_m[l], __popc(ball));
            base = __shfl_sync(0xffffffffu, base, ldr);
            if (gtt) {
                int rank = __popc(ball & ((1u << lane) - 1u));
                g_comp[l][base + rank] =
                    make_uint2(__float_as_uint(prob),
                               __float_as_uint(valid ? nll : -1e30f));
            }
        }
    }

    // ---- boundary BCE (fused) ----
    float tb = bgt[pix];
    const float* pb = bp + (size_t)b * HI * WI;
    int x1 = min(x0 + 1, WI - 1);
    float v00 = pb[y0 * WI + x0], v01 = pb[y0 * WI + x1];
    float v10 = pb[y1 * WI + x0], v11 = pb[y1 * WI + x1];
    float top = fmaf(wx, v01 - v00, v00);
    float bot = fmaf(wx, v11 - v10, v10);
    float p   = fmaf(wy, bot - top, top);

    bool  isP = (tb == 1.0f), isN = (tb == 0.0f);
    float r4 = isP ? fmaxf(-__log2f(p) * LN2f, 0.f)       : 0.f;  // -log(p) clamped at 100 below
    float r5 = isN ? fmaxf(-__log2f(1.f - p) * LN2f, 0.f) : 0.f;
    r4 = fminf(r4, 100.f);
    r5 = fminf(r5, 100.f);

    // ---- block reduce: counts via ballot/popc, sums via shfl ----
    float c0 = (float)__popc(__ballot_sync(~0u, le_v[0]));
    float c1 = (float)__popc(__ballot_sync(~0u, le_v[1]));
    float cp = (float)__popc(__ballot_sync(~0u, isP));
    float cn = (float)__popc(__ballot_sync(~0u, isN));
    float r1 = nll_v[0], r3 = nll_v[1];
    #pragma unroll
    for (int o = 16; o > 0; o >>= 1) {
        r1 += __shfl_down_sync(~0u, r1, o);
        r3 += __shfl_down_sync(~0u, r3, o);
        r4 += __shfl_down_sync(~0u, r4, o);
        r5 += __shfl_down_sync(~0u, r5, o);
    }
    if (lane == 0) {
        sred[warp][0] = c0; sred[warp][1] = r1; sred[warp][2] = c1; sred[warp][3] = r3;
        sred[warp][4] = r4; sred[warp][5] = r5; sred[warp][6] = cp; sred[warp][7] = cn;
    }
    __syncthreads();
    if (tid < 8) {
        float acc = 0.f;
        #pragma unroll
        for (int w = 0; w < 8; w++) acc += sred[w][tid];
        int blk = blockIdx.x + 4 * (blockIdx.y + 512 * blockIdx.z);
        if (tid < 4) atomicAdd(&g_oh[tid >> 1][tid & 1][blk & 63], acc);
        else         atomicAdd(&g_bce4[b][tid - 4][blk & 31], acc);
    }
}

// ---------------- tail: fallback select + finalize + scratch reset ----------------
__global__ __launch_bounds__(1024) void tail_kernel(float* __restrict__ out, int K) {
    __shared__ unsigned hist[2048];
    __shared__ int      s_r;
    __shared__ unsigned s_pref;
    __shared__ float    s_bcast;
    __shared__ float    redS[32], redC[32];
    __shared__ double   shb[4];
    __shared__ float    shoh[2][4];
    __shared__ float    s_ex[2][2];

    int tid = threadIdx.x, lane = tid & 31, w = tid >> 5;

    if (tid < 2) { s_ex[tid][0] = 0.f; s_ex[tid][1] = 0.f; }
    __syncthreads();

    for (int l = 0; l < 2; l++) {
        if (tid == 0) {
            float c = 0.f;
            #pragma unroll
            for (int i = 0; i < 64; i++) c += g_oh[l][0][i];
            s_bcast = c;
        }
        __syncthreads();
        int cLE = (int)(s_bcast + 0.5f);
        __syncthreads();
        if (cLE >= K) continue;                 // common path: thr = 0.7 exactly

        int m = g_m[l];
        if (tid == 0) { s_r = K - 1 - cLE; s_pref = 0u; }
        __syncthreads();

        #pragma unroll
        for (int lev = 0; lev < 3; lev++) {
            for (int i = tid; i < 2048; i += 1024) hist[i] = 0u;
            __syncthreads();
            unsigned pref = s_pref;
            for (int i = tid; i < m; i += 1024) {
                unsigned bits = g_comp[l][i].x;
                bool ok; unsigned bin;
                if (lev == 0)      { ok = true;                 bin = bits >> 21; }
                else if (lev == 1) { ok = (bits >> 21) == pref; bin = (bits >> 10) & 0x7FFu; }
                else               { ok = (bits >> 10) == pref; bin = bits & 0x3FFu; }
                if (ok) atomicAdd(&hist[bin], 1u);
            }
            __syncthreads();
            if (tid == 0) {
                int rr = s_r; unsigned cum = 0u;
                int nb = (lev == 2) ? 1024 : 2048;
                for (int i2 = 0; i2 < nb; i2++) {
                    unsigned h = hist[i2];
                    if ((int)(cum + h) > rr) {
                        s_pref = (lev == 0) ? (unsigned)i2
                               : (lev == 1) ? ((pref << 11) | (unsigned)i2)
                                            : ((pref << 10) | (unsigned)i2);
                        s_r = rr - (int)cum;
                        break;
                    }
                    cum += h;
                }
            }
            __syncthreads();
        }
        unsigned thr_bits = s_pref;

        float es = 0.f, ec = 0.f;
        for (int i = tid; i < m; i += 1024) {
            uint2 e = g_comp[l][i];
            float nl = __uint_as_float(e.y);
            if (e.x <= thr_bits && nl > -1e29f) { es += nl; ec += 1.f; }
        }
        #pragma unroll
        for (int o = 16; o > 0; o >>= 1) {
            es += __shfl_down_sync(~0u, es, o);
            ec += __shfl_down_sync(~0u, ec, o);
        }
        if (lane == 0) { redS[w] = es; redC[w] = ec; }
        __syncthreads();
        if (tid == 0) {
            float ts = 0.f, tc2 = 0.f;
            #pragma unroll
            for (int i = 0; i < 32; i++) { ts += redS[i]; tc2 += redC[i]; }
            s_ex[l][0] = ts; s_ex[l][1] = tc2;
        }
        __syncthreads();
    }

    // ---- finalize (first 128 threads) ----
    if (tid < 128) {
        float bs1  = g_bce4[w][0][lane];
        float bs0  = g_bce4[w][1][lane];
        float bpos = g_bce4[w][2][lane];
        float bneg = g_bce4[w][3][lane];
        float oc = 0.f, os = 0.f, oc1 = 0.f, os1 = 0.f;
        if (w < 2) {
            oc  = g_oh[0][0][tid]; os  = g_oh[0][1][tid];
            oc1 = g_oh[1][0][tid]; os1 = g_oh[1][1][tid];
        }
        #pragma unroll
        for (int o = 16; o > 0; o >>= 1) {
            bs1 += __shfl_down_sync(~0u, bs1, o); bs0 += __shfl_down_sync(~0u, bs0, o);
            bpos += __shfl_down_sync(~0u, bpos, o); bneg += __shfl_down_sync(~0u, bneg, o);
            oc += __shfl_down_sync(~0u, oc, o); os += __shfl_down_sync(~0u, os, o);
            oc1 += __shfl_down_sync(~0u, oc1, o); os1 += __shfl_down_sync(~0u, os1, o);
        }
        if (lane == 0) {
            double denom = (double)bpos + (double)bneg;
            shb[w] = ((double)bneg * (double)bs1 + (double)bpos * (double)bs0) / denom;
            if (w < 2) { shoh[w][0] = oc; shoh[w][1] = os; shoh[w][2] = oc1; shoh[w][3] = os1; }
        }
    }
    __syncthreads();
    if (tid == 0) {
        double cnt0 = (double)shoh[0][0] + (double)shoh[1][0] + (double)s_ex[0][1];
        double sum0 = (double)shoh[0][1] + (double)shoh[1][1] + (double)s_ex[0][0];
        double cnt1 = (double)shoh[0][2] + (double)shoh[1][2] + (double)s_ex[1][1];
        double sum1 = (double)shoh[0][3] + (double)shoh[1][3] + (double)s_ex[1][0];
        if (cnt0 < 1.0) cnt0 = 1.0;
        if (cnt1 < 1.0) cnt1 = 1.0;
        double bce = (shb[0] + shb[1] + shb[2] + shb[3]) / (double)NPIX;
        out[0] = (float)(sum0 / cnt0 + sum1 / cnt1 + bce);
    }

    // ---- reset scratch for next call / graph replay ----
    __syncthreads();
    {
        float* oh = &g_oh[0][0][0];
        if (tid < 256) oh[tid] = 0.f;
        float* bb = &g_bce4[0][0][0];
        if (tid < 512) bb[tid] = 0.f;
        if (tid < 2) g_m[tid] = 0;
    }
}

// ---------------- launch ----------------
extern "C" void kernel_launch(void* const* d_in, const int* in_sizes, int n_in,
                              void* d_out, int out_size)
{
    const float* mainp   = (const float*)d_in[0];
    const float* coarsep = (const float*)d_in[1];
    const float* bp      = (const float*)d_in[2];
    const int*   seg     = (const int*)d_in[3];
    const float* bgt     = (const float*)d_in[4];

    int nseg = in_sizes[3];
    int K = (nseg < 100000) ? nseg : 100000;

    compute_kernel<<<dim3(WO / 256, HO, B_), 256>>>(mainp, coarsep, seg, bp, bgt);
    tail_kernel<<<1, 1024>>>((float*)d_out, K);
}

// round 5
// speedup vs baseline: 1.2677x; 1.2497x over previous
#include <cuda_runtime.h>

#define B_   4
#define C_   19
#define HI   64
#define WI   128
#define HO   512
#define WO   1024
#define NPIX   (B_*HO*WO)
#define LOG2E  1.4426950408889634f
#define LN2f   0.6931471805599453f

typedef unsigned long long ull;

// ---------------- device scratch (zero at module load; tail kernel re-zeroes) ----
__device__ float    g_oh[2][2][64];     // [loss][{cnt,sum}][slot]
__device__ float    g_bce4[B_][4][32];  // [sample][{S1,S0,pos,neg}][slot]
__device__ int      g_m[2];             // compacted count per loss (probs > 0.7)
__device__ uint2    g_comp[2][NPIX];    // {prob_bits, nll_bits or -1e30 sentinel}

__device__ __forceinline__ float ex2(float x) {
    float y; asm("ex2.approx.f32 %0, %1;" : "=f"(y) : "f"(x)); return y;
}
__device__ __forceinline__ float lg2(float x) {
    float y; asm("lg2.approx.f32 %0, %1;" : "=f"(y) : "f"(x)); return y;
}
__device__ __forceinline__ ull pack2(float v) {
    ull r; asm("mov.b64 %0, {%1, %1};" : "=l"(r) : "f"(v)); return r;
}
__device__ __forceinline__ ull mul2(ull a, ull b) {
    ull r; asm("mul.rn.f32x2 %0, %1, %2;" : "=l"(r) : "l"(a), "l"(b)); return r;
}
__device__ __forceinline__ ull fma2(ull a, ull b, ull c) {
    ull r; asm("fma.rn.f32x2 %0, %1, %2, %3;" : "=l"(r) : "l"(a), "l"(b), "l"(c)); return r;
}
__device__ __forceinline__ void unpack2(ull v, float& lo, float& hi) {
    asm("mov.b64 {%0, %1}, %2;" : "=f"(lo), "=f"(hi) : "l"(v));
}

// ---------------- fused: upsample + softmax + OHEM accumulate + compaction + BCE ----
__global__ __launch_bounds__(256) void compute_kernel(
    const float* __restrict__ mainp,
    const float* __restrict__ coarsep,
    const int*   __restrict__ seg,
    const float* __restrict__ bp,
    const float* __restrict__ bgt)
{
    __shared__ float2 pr[C_][40];      // (main, coarse) vertically-lerped * log2e
    __shared__ float  sred[8][8];

    const float SY = 63.f / 511.f;
    const float SX = 127.f / 1023.f;

    const int tid  = threadIdx.x;
    const int lane = tid & 31;
    const int warp = tid >> 5;
    const int oy = blockIdx.y;
    const int b  = blockIdx.z;
    const int xs = blockIdx.x * 256;

    float fy = oy * SY;
    int   y0 = (int)fy;
    int   y1 = min(y0 + 1, HI - 1);
    float wy = fy - (float)y0;

    int xbase = (int)((float)xs * SX);
    int xlast = (int)((float)(xs + 255) * SX);
    int ntot  = xlast + 2 - xbase;          // columns [xbase, xlast+1], <= 34

    const float* p0 = mainp   + (size_t)b * C_ * HI * WI;
    const float* p1 = coarsep + (size_t)b * C_ * HI * WI;

    // stage 1: vertical lerp for both losses into packed float2 (pre-scaled by log2e)
    for (int idx = tid; idx < C_ * ntot; idx += 256) {
        int c  = idx / ntot;
        int xo = idx - c * ntot;
        int xi = min(xbase + xo, WI - 1);
        int o0 = c * HI * WI + y0 * WI + xi;
        int o1 = c * HI * WI + y1 * WI + xi;
        float a0 = p0[o0], a1 = p0[o1];
        float b0 = p1[o0], b1 = p1[o1];
        pr[c][xo] = make_float2((a0 * (1.f - wy) + a1 * wy) * LOG2E,
                                (b0 * (1.f - wy) + b1 * wy) * LOG2E);
    }
    __syncthreads();

    int   ox = xs + tid;
    float fx = (float)ox * SX;
    int   x0 = (int)fx;
    float wx = fx - (float)x0;
    int   i0 = x0 - xbase;

    int  pix   = (b * HO + oy) * WO + ox;
    int  t     = seg[pix];
    bool valid = (t != 255);
    int  tc    = valid ? t : 0;
    if (tc >= C_) tc = C_ - 1;

    const ull* prq = reinterpret_cast<const ull*>(&pr[0][0]);
    ull WX = pack2(wx);
    ull W1 = pack2(1.f - wx);

    // packed horizontal lerp + dual softmax sums
    float sm0 = 0.f, sm1 = 0.f, sc0 = 0.f, sc1 = 0.f;
    #pragma unroll
    for (int c = 0; c < C_; c++) {
        ull A = prq[c * 40 + i0];
        ull Bv = prq[c * 40 + i0 + 1];
        ull V = fma2(WX, Bv, mul2(W1, A));
        float vm, vc; unpack2(V, vm, vc);
        float em = ex2(vm), ec = ex2(vc);
        if (c & 1) { sm1 += em; sc1 += ec; }
        else       { sm0 += em; sc0 += ec; }
    }
    float s_main = sm0 + sm1, s_coar = sc0 + sc1;

    // target-class logits (both losses, packed)
    float vtm, vtc;
    {
        ull A = prq[tc * 40 + i0];
        ull Bv = prq[tc * 40 + i0 + 1];
        ull V = fma2(WX, Bv, mul2(W1, A));
        unpack2(V, vtm, vtc);
    }

    float nll_v[2]; bool le_v[2];
    float lp2m = vtm - lg2(s_main);
    float lp2c = vtc - lg2(s_coar);
    #pragma unroll
    for (int l = 0; l < 2; l++) {
        float lp2  = l ? lp2c : lp2m;
        float prob = ex2(lp2);
        float nll  = -lp2 * LN2f;
        if (!valid) prob = 1.0f;

        le_v[l]  = valid && (prob <= 0.7f);
        nll_v[l] = le_v[l] ? nll : 0.f;

        bool gtt = prob > 0.7f;
        unsigned ball = __ballot_sync(0xffffffffu, gtt);
        if (ball) {
            int ldr = __ffs(ball) - 1;
            int base = 0;
            if (lane == ldr) base = atomicAdd(&g_m[l], __popc(ball));
            base = __shfl_sync(0xffffffffu, base, ldr);
            if (gtt) {
                int rank = __popc(ball & ((1u << lane) - 1u));
                g_comp[l][base + rank] =
                    make_uint2(__float_as_uint(prob),
                               __float_as_uint(valid ? nll : -1e30f));
            }
        }
    }

    // ---- boundary BCE (fused) ----
    float tb = bgt[pix];
    const float* pb = bp + (size_t)b * HI * WI;
    int x1 = min(x0 + 1, WI - 1);
    float v00 = pb[y0 * WI + x0], v01 = pb[y0 * WI + x1];
    float v10 = pb[y1 * WI + x0], v11 = pb[y1 * WI + x1];
    float top = v00 * (1.f - wx) + v01 * wx;
    float bot = v10 * (1.f - wx) + v11 * wx;
    float p   = top * (1.f - wy) + bot * wy;

    bool  isP = (tb == 1.0f), isN = (tb == 0.0f);
    float r4 = isP ? fminf(fmaxf(-lg2(p) * LN2f, 0.f), 100.f)       : 0.f;
    float r5 = isN ? fminf(fmaxf(-lg2(1.f - p) * LN2f, 0.f), 100.f) : 0.f;

    // ---- block reduce: counts via ballot/popc, sums via shfl ----
    float c0 = (float)__popc(__ballot_sync(~0u, le_v[0]));
    float c1 = (float)__popc(__ballot_sync(~0u, le_v[1]));
    float cp = (float)__popc(__ballot_sync(~0u, isP));
    float cn = (float)__popc(__ballot_sync(~0u, isN));
    float r1 = nll_v[0], r3 = nll_v[1];
    #pragma unroll
    for (int o = 16; o > 0; o >>= 1) {
        r1 += __shfl_down_sync(~0u, r1, o);
        r3 += __shfl_down_sync(~0u, r3, o);
        r4 += __shfl_down_sync(~0u, r4, o);
        r5 += __shfl_down_sync(~0u, r5, o);
    }
    if (lane == 0) {
        sred[warp][0] = c0; sred[warp][1] = r1; sred[warp][2] = c1; sred[warp][3] = r3;
        sred[warp][4] = r4; sred[warp][5] = r5; sred[warp][6] = cp; sred[warp][7] = cn;
    }
    __syncthreads();
    if (tid < 8) {
        float acc = 0.f;
        #pragma unroll
        for (int w = 0; w < 8; w++) acc += sred[w][tid];
        int blk = blockIdx.x + 4 * (blockIdx.y + 512 * blockIdx.z);
        if (tid < 4) atomicAdd(&g_oh[tid >> 1][tid & 1][blk & 63], acc);
        else         atomicAdd(&g_bce4[b][tid - 4][blk & 31], acc);
    }
}

// ---------------- tail: fallback select + finalize + scratch reset ----------------
__global__ __launch_bounds__(1024) void tail_kernel(float* __restrict__ out, int K) {
    __shared__ unsigned hist[2048];
    __shared__ int      s_r;
    __shared__ unsigned s_pref;
    __shared__ float    s_cle[2];
    __shared__ float    redS[32], redC[32];
    __shared__ double   shb[4];
    __shared__ float    shoh[2][4];
    __shared__ float    s_ex[2][2];

    int tid = threadIdx.x, lane = tid & 31, w = tid >> 5;

    if (tid < 2) { s_ex[tid][0] = 0.f; s_ex[tid][1] = 0.f; }
    // parallel cLE sums: threads 0..127 cover [loss][slot]
    if (tid < 128) {
        float v = g_oh[tid >> 6][0][tid & 63];
        #pragma unroll
        for (int o = 16; o > 0; o >>= 1) v += __shfl_down_sync(~0u, v, o);
        if (lane == 0) redS[w] = v;   // w in 0..3
    }
    __syncthreads();
    if (tid < 2) s_cle[tid] = redS[tid * 2] + redS[tid * 2 + 1];
    __syncthreads();

    for (int l = 0; l < 2; l++) {
        int cLE = (int)(s_cle[l] + 0.5f);
        if (cLE >= K) continue;                 // common path: thr = 0.7 exactly

        int m = g_m[l];
        if (tid == 0) { s_r = K - 1 - cLE; s_pref = 0u; }
        __syncthreads();

        #pragma unroll
        for (int lev = 0; lev < 3; lev++) {
            for (int i = tid; i < 2048; i += 1024) hist[i] = 0u;
            __syncthreads();
            unsigned pref = s_pref;
            for (int i = tid; i < m; i += 1024) {
                unsigned bits = g_comp[l][i].x;
                bool ok; unsigned bin;
                if (lev == 0)      { ok = true;                 bin = bits >> 21; }
                else if (lev == 1) { ok = (bits >> 21) == pref; bin = (bits >> 10) & 0x7FFu; }
                else               { ok = (bits >> 10) == pref; bin = bits & 0x3FFu; }
                if (ok) atomicAdd(&hist[bin], 1u);
            }
            __syncthreads();
            if (tid == 0) {
                int rr = s_r; unsigned cum = 0u;
                int nb = (lev == 2) ? 1024 : 2048;
                for (int i2 = 0; i2 < nb; i2++) {
                    unsigned h = hist[i2];
                    if ((int)(cum + h) > rr) {
                        s_pref = (lev == 0) ? (unsigned)i2
                               : (lev == 1) ? ((pref << 11) | (unsigned)i2)
                                            : ((pref << 10) | (unsigned)i2);
                        s_r = rr - (int)cum;
                        break;
                    }
                    cum += h;
                }
            }
            __syncthreads();
        }
        unsigned thr_bits = s_pref;

        float es = 0.f, ec = 0.f;
        for (int i = tid; i < m; i += 1024) {
            uint2 e = g_comp[l][i];
            float nl = __uint_as_float(e.y);
            if (e.x <= thr_bits && nl > -1e29f) { es += nl; ec += 1.f; }
        }
        #pragma unroll
        for (int o = 16; o > 0; o >>= 1) {
            es += __shfl_down_sync(~0u, es, o);
            ec += __shfl_down_sync(~0u, ec, o);
        }
        if (lane == 0) { redS[w] = es; redC[w] = ec; }
        __syncthreads();
        if (tid == 0) {
            float ts = 0.f, tc2 = 0.f;
            #pragma unroll
            for (int i = 0; i < 32; i++) { ts += redS[i]; tc2 += redC[i]; }
            s_ex[l][0] = ts; s_ex[l][1] = tc2;
        }
        __syncthreads();
    }

    // ---- finalize (first 128 threads) ----
    if (tid < 128) {
        float bs1  = g_bce4[w][0][lane];
        float bs0  = g_bce4[w][1][lane];
        float bpos = g_bce4[w][2][lane];
        float bneg = g_bce4[w][3][lane];
        float oc = 0.f, os = 0.f, oc1 = 0.f, os1 = 0.f;
        if (w < 2) {
            oc  = g_oh[0][0][tid]; os  = g_oh[0][1][tid];
            oc1 = g_oh[1][0][tid]; os1 = g_oh[1][1][tid];
        }
        #pragma unroll
        for (int o = 16; o > 0; o >>= 1) {
            bs1 += __shfl_down_sync(~0u, bs1, o); bs0 += __shfl_down_sync(~0u, bs0, o);
            bpos += __shfl_down_sync(~0u, bpos, o); bneg += __shfl_down_sync(~0u, bneg, o);
            oc += __shfl_down_sync(~0u, oc, o); os += __shfl_down_sync(~0u, os, o);
            oc1 += __shfl_down_sync(~0u, oc1, o); os1 += __shfl_down_sync(~0u, os1, o);
        }
        if (lane == 0) {
            double denom = (double)bpos + (double)bneg;
            shb[w] = ((double)bneg * (double)bs1 + (double)bpos * (double)bs0) / denom;
            if (w < 2) { shoh[w][0] = oc; shoh[w][1] = os; shoh[w][2] = oc1; shoh[w][3] = os1; }
        }
    }
    __syncthreads();
    if (tid == 0) {
        double cnt0 = (double)shoh[0][0] + (double)shoh[1][0] + (double)s_ex[0][1];
        double sum0 = (double)shoh[0][1] + (double)shoh[1][1] + (double)s_ex[0][0];
        double cnt1 = (double)shoh[0][2] + (double)shoh[1][2] + (double)s_ex[1][1];
        double sum1 = (double)shoh[0][3] + (double)shoh[1][3] + (double)s_ex[1][0];
        if (cnt0 < 1.0) cnt0 = 1.0;
        if (cnt1 < 1.0) cnt1 = 1.0;
        double bce = (shb[0] + shb[1] + shb[2] + shb[3]) / (double)NPIX;
        out[0] = (float)(sum0 / cnt0 + sum1 / cnt1 + bce);
    }

    // ---- reset scratch for next call / graph replay ----
    __syncthreads();
    {
        float* oh = &g_oh[0][0][0];
        if (tid < 256) oh[tid] = 0.f;
        float* bb = &g_bce4[0][0][0];
        if (tid < 512) bb[tid] = 0.f;
        if (tid < 2) g_m[tid] = 0;
    }
}

// ---------------- launch ----------------
extern "C" void kernel_launch(void* const* d_in, const int* in_sizes, int n_in,
                              void* d_out, int out_size)
{
    const float* mainp   = (const float*)d_in[0];
    const float* coarsep = (const float*)d_in[1];
    const float* bp      = (const float*)d_in[2];
    const int*   seg     = (const int*)d_in[3];
    const float* bgt     = (const float*)d_in[4];

    int nseg = in_sizes[3];
    int K = (nseg < 100000) ? nseg : 100000;

    compute_kernel<<<dim3(WO / 256, HO, B_), 256>>>(mainp, coarsep, seg, bp, bgt);
    tail_kernel<<<1, 1024>>>((float*)d_out, K);
}